// round 17
// baseline (speedup 1.0000x reference)
#include <cuda_runtime.h>
#include <cuda_fp16.h>
#include <cstdint>
#include <string.h>
#include <math.h>

#define B_SZ 2
#define P_SZ 2048
#define M_SZ 1024
#define H_SZ 16
#define D_SZ 64
#define N3_SZ 3072
#define R_SZ (B_SZ * P_SZ)      // 4096
#define K_SZ M_SZ               // 1024
#define BH_SZ (B_SZ * H_SZ)     // 32

// ---------------- scratch (__device__ globals) -----------------------------
__device__ __half g_xh [(size_t)R_SZ * K_SZ];
__device__ __half g_wa [(size_t)N3_SZ * K_SZ];
__device__ __half g_wp [(size_t)M_SZ * K_SZ];
__device__ __half g_qh[(size_t)BH_SZ * P_SZ * D_SZ];
__device__ __half g_ql[(size_t)BH_SZ * P_SZ * D_SZ];
__device__ __half g_k [(size_t)BH_SZ * P_SZ * D_SZ];
__device__ __half g_v [(size_t)BH_SZ * P_SZ * D_SZ];
__device__ __half g_z [(size_t)R_SZ * K_SZ];

// ---------------- PTX helpers (base ISA) -----------------------------------
__device__ __forceinline__ uint32_t smem_u32(const void* p) {
    uint32_t a;
    asm("{ .reg .u64 t; cvta.to.shared.u64 t, %1; cvt.u32.u64 %0, t; }" : "=r"(a) : "l"(p));
    return a;
}
__device__ __forceinline__ void ldsm4(uint32_t* r, uint32_t addr) {
    asm volatile("ldmatrix.sync.aligned.m8n8.x4.shared.b16 {%0,%1,%2,%3}, [%4];"
                 : "=r"(r[0]), "=r"(r[1]), "=r"(r[2]), "=r"(r[3]) : "r"(addr));
}
__device__ __forceinline__ void ldsm4t(uint32_t* r, uint32_t addr) {
    asm volatile("ldmatrix.sync.aligned.m8n8.x4.trans.shared.b16 {%0,%1,%2,%3}, [%4];"
                 : "=r"(r[0]), "=r"(r[1]), "=r"(r[2]), "=r"(r[3]) : "r"(addr));
}
__device__ __forceinline__ void mma16816(float* c, const uint32_t* a, const uint32_t* b) {
    asm volatile(
        "mma.sync.aligned.m16n8k16.row.col.f32.f16.f16.f32 "
        "{%0,%1,%2,%3}, {%4,%5,%6,%7}, {%8,%9}, {%0,%1,%2,%3};"
        : "+f"(c[0]), "+f"(c[1]), "+f"(c[2]), "+f"(c[3])
        : "r"(a[0]), "r"(a[1]), "r"(a[2]), "r"(a[3]), "r"(b[0]), "r"(b[1]));
}
__device__ __forceinline__ void cpasync16(uint32_t saddr, const void* gaddr) {
    asm volatile("cp.async.cg.shared.global [%0], [%1], 16;" :: "r"(saddr), "l"(gaddr) : "memory");
}
__device__ __forceinline__ void sts32(uint32_t addr, uint32_t v) {
    asm volatile("st.shared.b32 [%0], %1;" :: "r"(addr), "r"(v) : "memory");
}
__device__ __forceinline__ void sts64(uint32_t addr, float a, float b) {
    asm volatile("st.shared.v2.f32 [%0], {%1,%2};" :: "r"(addr), "f"(a), "f"(b) : "memory");
}
__device__ __forceinline__ uint4 lds128(uint32_t addr) {
    uint4 v;
    asm volatile("ld.shared.v4.b32 {%0,%1,%2,%3}, [%4];"
                 : "=r"(v.x), "=r"(v.y), "=r"(v.z), "=r"(v.w) : "r"(addr));
    return v;
}
__device__ __forceinline__ void split2h(float a, float b, uint32_t& hu, uint32_t& lu) {
    __half ha = __float2half_rn(a), hb = __float2half_rn(b);
    float ra = a - __half2float(ha), rb = b - __half2float(hb);
    __half2 H = __halves2half2(ha, hb);
    __half2 L = __floats2half2_rn(ra, rb);
    memcpy(&hu, &H, 4); memcpy(&lu, &L, 4);
}
__device__ __forceinline__ uint32_t pack2h(float a, float b) {
    __half2 H = __floats2half2_rn(a, b);
    uint32_t u; memcpy(&u, &H, 4); return u;
}

// ---------------- fp32 -> fp16 convert -------------------------------------
struct alignas(8) h16x4 { __half2 a, b; };

__global__ __launch_bounds__(256) void convert_kernel(
    const float* __restrict__ in, __half* __restrict__ out, int n4)
{
    int i = blockIdx.x * 256 + threadIdx.x;
    if (i >= n4) return;
    float4 v = ((const float4*)in)[i];
    h16x4 H;
    H.a = __floats2half2_rn(v.x, v.y);
    H.b = __floats2half2_rn(v.z, v.w);
    ((h16x4*)out)[i] = H;
}

__global__ __launch_bounds__(256) void tsingle_kernel(
    const float* __restrict__ W, __half* __restrict__ out, int K, int N)
{
    __shared__ float s[32][33];
    const int n0 = blockIdx.x * 32, k0 = blockIdx.y * 32;
    const int tx = threadIdx.x & 31, ty = threadIdx.x >> 5;
    #pragma unroll
    for (int i = 0; i < 4; i++)
        s[ty + 8 * i][tx] = W[(size_t)(k0 + ty + 8 * i) * N + n0 + tx];
    __syncthreads();
    #pragma unroll
    for (int i = 0; i < 4; i++) {
        int r = ty + 8 * i;
        out[(size_t)(n0 + r) * K + k0 + tx] = __float2half_rn(s[tx][r]);
    }
}

// ---------------- fp16 1-term mma GEMM, 4-stage pipeline -------------------
#define GK_CH   (K_SZ / 32)
#define GT_TILE 10240                  // 128 rows * 80 B
#define GT_STG  (2 * GT_TILE)          // A, B per stage
#define GT_SMEM 81920                  // 4 stages (epilogue needs <= 69632)

// Q pre-scale: 1/sqrt(64) * log2(e)
#define QSCALE (0.125f * 1.44269504088896f)

template<int MODE>
__global__ __launch_bounds__(128) void gemm_mma_kernel(
    const __half* __restrict__ A, const __half* __restrict__ B,
    const float* __restrict__ bias, float* __restrict__ C, int N,
    __half* __restrict__ qh, __half* __restrict__ ql,
    __half* __restrict__ kk, __half* __restrict__ vv)
{
    extern __shared__ char smraw[];
    const uint32_t sbase = smem_u32(smraw);

    const int tid = threadIdx.x;
    const int wid = tid >> 5, lane = tid & 31;
    const int wm = wid & 1, wn = wid >> 1;
    const int g = lane >> 2, t = lane & 3;
    const int row0 = blockIdx.y << 7;
    const int col0 = blockIdx.x << 7;

    const __half* srcs[2] = {A, B};

    auto load_part = [&](int c, int s, int arr) {
        const int k0 = c << 5;
        const __half* src = srcs[arr];
        const int rbase = (arr == 0) ? row0 : col0;
        const uint32_t tb = sbase + (uint32_t)s * GT_STG + (uint32_t)arr * GT_TILE;
        #pragma unroll
        for (int it = 0; it < 4; it++) {
            int id = it * 128 + tid, r = id >> 2, q = id & 3;
            cpasync16(tb + (uint32_t)(r * 80 + q * 16),
                      src + (size_t)(rbase + r) * K_SZ + k0 + q * 8);
        }
    };

    float acc[4][8][4] = {};
    const int a_row = lane & 15;
    const int a_cb  = (lane >> 4) << 4;
    const int b2_row = (lane & 7) + ((lane >> 4) << 3);
    const int b2_cb  = ((lane >> 3) & 1) << 4;

    // prologue: chunks 0,1,2 in flight (3 groups)
    load_part(0, 0, 0); load_part(0, 0, 1);
    asm volatile("cp.async.commit_group;" ::: "memory");
    load_part(1, 1, 0); load_part(1, 1, 1);
    asm volatile("cp.async.commit_group;" ::: "memory");
    load_part(2, 2, 0); load_part(2, 2, 1);
    asm volatile("cp.async.commit_group;" ::: "memory");

    int stage = 0;
    for (int c = 0; c < GK_CH; c++) {
        asm volatile("cp.async.wait_group 2;" ::: "memory");   // chunk c ready
        __syncthreads();

        const uint32_t stg = sbase + (uint32_t)stage * GT_STG;
        const uint32_t tA = stg, tB = stg + GT_TILE;
        const bool more = (c + 3 < GK_CH);
        const int ws = (stage + 3) & 3;                        // (c+3) % 4

        #pragma unroll
        for (int ks = 0; ks < 2; ks++) {
            const int kb = ks << 5;
            uint32_t af[4][4], bf[4][4];
            #pragma unroll
            for (int mt = 0; mt < 4; mt++)
                ldsm4(af[mt], tA + (uint32_t)((wm * 64 + mt * 16 + a_row) * 80 + kb + a_cb));
            #pragma unroll
            for (int np = 0; np < 4; np++)
                ldsm4(bf[np], tB + (uint32_t)((wn * 64 + np * 16 + b2_row) * 80 + kb + b2_cb));
            if (more) load_part(c + 3, ws, ks);
            #pragma unroll
            for (int np = 0; np < 4; np++)
                #pragma unroll
                for (int mt = 0; mt < 4; mt++) {
                    mma16816(acc[mt][2 * np],     af[mt], &bf[np][0]);
                    mma16816(acc[mt][2 * np + 1], af[mt], &bf[np][2]);
                }
        }
        asm volatile("cp.async.commit_group;" ::: "memory");
        stage = (stage + 1) & 3;
    }
    asm volatile("cp.async.wait_group 0;" ::: "memory");
    __syncthreads();

    if (MODE == 1) {
        const int slice = col0 >> 10;
        const uint32_t hi0 = sbase, lo0 = sbase + 128 * 272;
        #pragma unroll
        for (int mt = 0; mt < 4; mt++) {
            const int rl = wm * 64 + mt * 16 + g;
            #pragma unroll
            for (int nt = 0; nt < 8; nt++) {
                const int cl = wn * 64 + nt * 8 + 2 * t;
                const int col = col0 + cl;
                const float b0 = bias[col], b1 = bias[col + 1];
                float v0 = acc[mt][nt][0] + b0, v1 = acc[mt][nt][1] + b1;
                float v2 = acc[mt][nt][2] + b0, v3 = acc[mt][nt][3] + b1;
                if (slice == 0) {
                    v0 *= QSCALE; v1 *= QSCALE; v2 *= QSCALE; v3 *= QSCALE;
                    uint32_t hu, lu;
                    split2h(v0, v1, hu, lu);
                    sts32(hi0 + (uint32_t)(rl * 272 + cl * 2), hu);
                    sts32(lo0 + (uint32_t)(rl * 272 + cl * 2), lu);
                    split2h(v2, v3, hu, lu);
                    sts32(hi0 + (uint32_t)((rl + 8) * 272 + cl * 2), hu);
                    sts32(lo0 + (uint32_t)((rl + 8) * 272 + cl * 2), lu);
                } else {
                    sts32(hi0 + (uint32_t)(rl * 272 + cl * 2), pack2h(v0, v1));
                    sts32(hi0 + (uint32_t)((rl + 8) * 272 + cl * 2), pack2h(v2, v3));
                }
            }
        }
        __syncthreads();
        #pragma unroll
        for (int it = 0; it < 16; it++) {
            const int id = it * 128 + tid, r = id >> 4, s = id & 15;
            const int col = col0 + s * 8;
            const int hh = (col >> 6) & 15, dd = col & 63;
            __half* oh = (slice == 0) ? qh : (slice == 1) ? kk : vv;
            const int row = row0 + r;
            const int ba = row >> 11, pa = row & 2047;
            const size_t oa = ((size_t)(ba * H_SZ + hh) * P_SZ + pa) * 64 + dd;
            uint4 vh4 = lds128(hi0 + (uint32_t)(r * 272 + s * 16));
            *(uint4*)(oh + oa) = vh4;
            if (slice == 0) {
                uint4 vl4 = lds128(lo0 + (uint32_t)(r * 272 + s * 16));
                *(uint4*)(ql + oa) = vl4;
            }
        }
    } else {
        #pragma unroll
        for (int mt = 0; mt < 4; mt++) {
            const int rl = wm * 64 + mt * 16 + g;
            #pragma unroll
            for (int nt = 0; nt < 8; nt++) {
                const int cl = wn * 64 + nt * 8 + 2 * t;
                const int col = col0 + cl;
                const float b0 = bias[col], b1 = bias[col + 1];
                sts64(sbase + (uint32_t)(rl * 528 + cl * 4),
                      acc[mt][nt][0] + b0, acc[mt][nt][1] + b1);
                sts64(sbase + (uint32_t)((rl + 8) * 528 + cl * 4),
                      acc[mt][nt][2] + b0, acc[mt][nt][3] + b1);
            }
        }
        __syncthreads();
        #pragma unroll
        for (int it = 0; it < 32; it++) {
            const int id = it * 128 + tid, r = id >> 5, s = id & 31;
            uint4 v = lds128(sbase + (uint32_t)(r * 528 + s * 16));
            *(uint4*)(C + (size_t)(row0 + r) * N + col0 + s * 4) = v;
        }
    }
}

// ---------------- fp16 flash attention: 3-stage KV pipeline ----------------
// region0 [0, 36864): Q hi/lo during prologue; stages 1 (at +0) and 2
//   (at +18432) afterwards; epilogue staging at +0.
// region1 [36864, 55296): stage 0.
#define AT_ROWB 144
#define AT_QTILE (128 * AT_ROWB)         // 18432
#define AT_KTILE (64 * AT_ROWB)          // 9216
#define AT_STG   (2 * AT_KTILE)          // 18432 (K, V)
#define AT_SMEM  (2 * AT_QTILE + AT_STG) // 55296

__global__ __launch_bounds__(128) void attn_mma_kernel(
    const __half* __restrict__ qh, const __half* __restrict__ ql,
    const __half* __restrict__ kk, const __half* __restrict__ vv,
    __half* __restrict__ z)
{
    extern __shared__ char smraw[];
    const uint32_t sb = smem_u32(smraw);
    const int tid = threadIdx.x, w = tid >> 5, lane = tid & 31;
    const int g = lane >> 2, t = lane & 3;
    const int qt = blockIdx.x, bh = blockIdx.y;
    const int q0 = qt << 7;
    const size_t hb = (size_t)bh * P_SZ * 64;

    const __half* kvsrc[2] = {kk + hb, vv + hb};
    auto stage_base = [&](int s) -> uint32_t {
        return (s == 0) ? sb + 2 * AT_QTILE : ((s == 1) ? sb : sb + AT_STG);
    };
    auto load_kv_part = [&](int kvt, int s, int a) {
        const uint32_t stg = stage_base(s);
        const size_t rb = (size_t)(kvt << 6) * 64;
        #pragma unroll
        for (int it = 0; it < 4; it++) {
            int id = it * 128 + tid, r = id >> 3, c = id & 7;
            cpasync16(stg + (uint32_t)(a * AT_KTILE + r * AT_ROWB + c * 16),
                      kvsrc[a] + rb + r * 64 + c * 8);
        }
    };

    {   // Q hi/lo into region 0 + KV0 into region 1
        const __half* Qh = qh + hb + (size_t)q0 * 64;
        const __half* Ql = ql + hb + (size_t)q0 * 64;
        #pragma unroll
        for (int it = 0; it < 8; it++) {
            int id = it * 128 + tid, r = id >> 3, c = id & 7;
            cpasync16(sb + (uint32_t)(r * AT_ROWB + c * 16), Qh + r * 64 + c * 8);
            cpasync16(sb + AT_QTILE + (uint32_t)(r * AT_ROWB + c * 16), Ql + r * 64 + c * 8);
        }
    }
    load_kv_part(0, 0, 0);
    load_kv_part(0, 0, 1);
    asm volatile("cp.async.commit_group;" ::: "memory");
    asm volatile("cp.async.wait_group 0;" ::: "memory");
    __syncthreads();

    // extract Q fragments; Q region becomes stages 1 and 2 afterwards
    uint32_t qhf[2][4][4], qlf[2][4][4];
    const int arow = (lane & 7) + ((lane >> 3) & 1) * 8;
    const int achk = lane >> 4;
    #pragma unroll
    for (int mt = 0; mt < 2; mt++)
        #pragma unroll
        for (int ks = 0; ks < 4; ks++) {
            uint32_t ad = sb + (uint32_t)((32 * w + 16 * mt + arow) * AT_ROWB +
                                          (2 * ks + achk) * 16);
            ldsm4(qhf[mt][ks], ad);
            ldsm4(qlf[mt][ks], ad + AT_QTILE);
        }
    __syncthreads();   // Q reads complete before any stage-1/2 write

    const int ntiles = 2 * qt + 2;
    if (ntiles > 1) { load_kv_part(1, 1, 0); load_kv_part(1, 1, 1); }
    asm volatile("cp.async.commit_group;" ::: "memory");

    float oacc[2][8][4] = {};
    float mrow[2][2], lrow[2][2];
    #pragma unroll
    for (int mt = 0; mt < 2; mt++) {
        mrow[mt][0] = -1e30f; mrow[mt][1] = -1e30f;
        lrow[mt][0] = 0.f;    lrow[mt][1] = 0.f;
    }
    const int wrow_min = q0 + 32 * w;
    const int wrow_max = wrow_min + 31;

    int st = 0;
    for (int kvt = 0; kvt < ntiles; kvt++) {
        if (kvt > 0) {
            asm volatile("cp.async.wait_group 1;" ::: "memory");
            __syncthreads();
        }
        const bool more2 = (kvt + 2 < ntiles);
        int st2 = st + 2; if (st2 >= 3) st2 -= 3;
        const int c_base = kvt << 6;
        if (c_base <= wrow_max) {
            const uint32_t kb = stage_base(st);

            float sacc[2][8][4] = {};
            uint32_t kf[2][2][4];
            #pragma unroll
            for (int cp = 0; cp < 2; cp++) {
                uint32_t ad = kb + (uint32_t)((lane & 7) * AT_ROWB + (4 * cp + (lane >> 3)) * 16);
                ldsm4(kf[0][cp], ad);
            }
            #pragma unroll
            for (int j = 0; j < 8; j++) {
                const int cur = j & 1, nxt = cur ^ 1;
                if (j < 7) {
                    #pragma unroll
                    for (int cp = 0; cp < 2; cp++) {
                        uint32_t ad = kb + (uint32_t)((8 * (j + 1) + (lane & 7)) * AT_ROWB +
                                                      (4 * cp + (lane >> 3)) * 16);
                        ldsm4(kf[nxt][cp], ad);
                    }
                }
                #pragma unroll
                for (int cp = 0; cp < 2; cp++)
                    #pragma unroll
                    for (int mt = 0; mt < 2; mt++) {
                        mma16816(sacc[mt][j], qhf[mt][2 * cp],     &kf[cur][cp][0]);
                        mma16816(sacc[mt][j], qhf[mt][2 * cp + 1], &kf[cur][cp][2]);
                    }
                #pragma unroll
                for (int cp = 0; cp < 2; cp++)
                    #pragma unroll
                    for (int mt = 0; mt < 2; mt++) {
                        mma16816(sacc[mt][j], qlf[mt][2 * cp],     &kf[cur][cp][0]);
                        mma16816(sacc[mt][j], qlf[mt][2 * cp + 1], &kf[cur][cp][2]);
                    }
            }
            if (more2) load_kv_part(kvt + 2, st2, 0);

            if (c_base + 63 > wrow_min) {
                #pragma unroll
                for (int mt = 0; mt < 2; mt++) {
                    const int lr0 = wrow_min + 16 * mt + g;
                    #pragma unroll
                    for (int j = 0; j < 8; j++) {
                        const int c0 = c_base + 8 * j + 2 * t;
                        if (c0     > lr0)     sacc[mt][j][0] = -1e30f;
                        if (c0 + 1 > lr0)     sacc[mt][j][1] = -1e30f;
                        if (c0     > lr0 + 8) sacc[mt][j][2] = -1e30f;
                        if (c0 + 1 > lr0 + 8) sacc[mt][j][3] = -1e30f;
                    }
                }
            }

            #pragma unroll
            for (int mt = 0; mt < 2; mt++) {
                float mx0 = -1e30f, mx1 = -1e30f;
                #pragma unroll
                for (int j = 0; j < 8; j++) {
                    mx0 = fmaxf(mx0, fmaxf(sacc[mt][j][0], sacc[mt][j][1]));
                    mx1 = fmaxf(mx1, fmaxf(sacc[mt][j][2], sacc[mt][j][3]));
                }
                mx0 = fmaxf(mx0, __shfl_xor_sync(0xffffffffu, mx0, 1));
                mx0 = fmaxf(mx0, __shfl_xor_sync(0xffffffffu, mx0, 2));
                mx1 = fmaxf(mx1, __shfl_xor_sync(0xffffffffu, mx1, 1));
                mx1 = fmaxf(mx1, __shfl_xor_sync(0xffffffffu, mx1, 2));
                const float mn0 = fmaxf(mrow[mt][0], mx0), mn1 = fmaxf(mrow[mt][1], mx1);
                const float al0 = exp2f(mrow[mt][0] - mn0), al1 = exp2f(mrow[mt][1] - mn1);
                float sum0 = 0.f, sum1 = 0.f;
                #pragma unroll
                for (int j = 0; j < 8; j++) {
                    sacc[mt][j][0] = exp2f(sacc[mt][j][0] - mn0);
                    sacc[mt][j][1] = exp2f(sacc[mt][j][1] - mn0);
                    sacc[mt][j][2] = exp2f(sacc[mt][j][2] - mn1);
                    sacc[mt][j][3] = exp2f(sacc[mt][j][3] - mn1);
                    sum0 += sacc[mt][j][0] + sacc[mt][j][1];
                    sum1 += sacc[mt][j][2] + sacc[mt][j][3];
                }
                sum0 += __shfl_xor_sync(0xffffffffu, sum0, 1);
                sum0 += __shfl_xor_sync(0xffffffffu, sum0, 2);
                sum1 += __shfl_xor_sync(0xffffffffu, sum1, 1);
                sum1 += __shfl_xor_sync(0xffffffffu, sum1, 2);
                lrow[mt][0] = lrow[mt][0] * al0 + sum0; mrow[mt][0] = mn0;
                lrow[mt][1] = lrow[mt][1] * al1 + sum1; mrow[mt][1] = mn1;
                #pragma unroll
                for (int j = 0; j < 8; j++) {
                    oacc[mt][j][0] *= al0; oacc[mt][j][1] *= al0;
                    oacc[mt][j][2] *= al1; oacc[mt][j][3] *= al1;
                }
            }

            #pragma unroll
            for (int s2 = 0; s2 < 4; s2++) {
                uint32_t pf[2][4];
                #pragma unroll
                for (int mt = 0; mt < 2; mt++) {
                    pf[mt][0] = pack2h(sacc[mt][2 * s2][0],     sacc[mt][2 * s2][1]);
                    pf[mt][1] = pack2h(sacc[mt][2 * s2][2],     sacc[mt][2 * s2][3]);
                    pf[mt][2] = pack2h(sacc[mt][2 * s2 + 1][0], sacc[mt][2 * s2 + 1][1]);
                    pf[mt][3] = pack2h(sacc[mt][2 * s2 + 1][2], sacc[mt][2 * s2 + 1][3]);
                }
                uint32_t vf[4][4];
                #pragma unroll
                for (int jp = 0; jp < 4; jp++) {
                    uint32_t ad = kb + AT_KTILE +
                        (uint32_t)((16 * s2 + (lane & 15)) * AT_ROWB + (2 * jp + (lane >> 4)) * 16);
                    ldsm4t(vf[jp], ad);
                }
                #pragma unroll
                for (int jp = 0; jp < 4; jp++)
                    #pragma unroll
                    for (int mt = 0; mt < 2; mt++) {
                        mma16816(oacc[mt][2 * jp],     pf[mt], &vf[jp][0]);
                        mma16816(oacc[mt][2 * jp + 1], pf[mt], &vf[jp][2]);
                    }
                if (more2 && s2 == 1) load_kv_part(kvt + 2, st2, 1);
            }
        } else if (more2) {
            load_kv_part(kvt + 2, st2, 0);
            load_kv_part(kvt + 2, st2, 1);
        }
        asm volatile("cp.async.commit_group;" ::: "memory");
        st++; if (st == 3) st = 0;
    }
    asm volatile("cp.async.wait_group 0;" ::: "memory");
    __syncthreads();

    // epilogue: z single fp16 staged at sb, coalesced 16B stores
    const uint32_t oh0 = sb;
    #pragma unroll
    for (int mt = 0; mt < 2; mt++) {
        const float i0 = 1.f / lrow[mt][0], i1 = 1.f / lrow[mt][1];
        const int rl = 32 * w + 16 * mt + g;
        #pragma unroll
        for (int j = 0; j < 8; j++) {
            const int cl = 8 * j + 2 * t;
            sts32(oh0 + (uint32_t)(rl * AT_ROWB + cl * 2),
                  pack2h(oacc[mt][j][0] * i0, oacc[mt][j][1] * i0));
            sts32(oh0 + (uint32_t)((rl + 8) * AT_ROWB + cl * 2),
                  pack2h(oacc[mt][j][2] * i1, oacc[mt][j][3] * i1));
        }
    }
    __syncthreads();
    const int b = bh >> 4, h = bh & 15;
    #pragma unroll
    for (int it = 0; it < 8; it++) {
        const int id = it * 128 + tid, r = id >> 3, s = id & 7;
        const size_t dst = ((size_t)b * P_SZ + q0 + r) * K_SZ + h * 64 + s * 8;
        uint4 vh4 = lds128(oh0 + (uint32_t)(r * AT_ROWB + s * 16));
        *(uint4*)(z + dst) = vh4;
    }
}

// ---------------------------------------------------------------------------
extern "C" void kernel_launch(void* const* d_in, const int* in_sizes, int n_in,
                              void* d_out, int out_size)
{
    (void)in_sizes; (void)n_in; (void)out_size;
    const float* x      = (const float*)d_in[0];
    const float* W_attn = (const float*)d_in[1];
    const float* b_attn = (const float*)d_in[2];
    const float* W_proj = (const float*)d_in[3];
    const float* b_proj = (const float*)d_in[4];
    float* out = (float*)d_out;

    __half *xh, *wa, *wp, *qh, *ql, *kk, *vv, *zz;
    cudaGetSymbolAddress((void**)&xh, g_xh);
    cudaGetSymbolAddress((void**)&wa, g_wa);
    cudaGetSymbolAddress((void**)&wp, g_wp);
    cudaGetSymbolAddress((void**)&qh, g_qh);
    cudaGetSymbolAddress((void**)&ql, g_ql);
    cudaGetSymbolAddress((void**)&kk, g_k);
    cudaGetSymbolAddress((void**)&vv, g_v);
    cudaGetSymbolAddress((void**)&zz, g_z);

    cudaFuncSetAttribute(gemm_mma_kernel<0>,
                         cudaFuncAttributeMaxDynamicSharedMemorySize, GT_SMEM);
    cudaFuncSetAttribute(gemm_mma_kernel<1>,
                         cudaFuncAttributeMaxDynamicSharedMemorySize, GT_SMEM);
    cudaFuncSetAttribute(attn_mma_kernel,
                         cudaFuncAttributeMaxDynamicSharedMemorySize, AT_SMEM);

    convert_kernel<<<(R_SZ * K_SZ / 4 + 255) / 256, 256>>>(x, xh, R_SZ * K_SZ / 4);
    tsingle_kernel<<<dim3(N3_SZ / 32, K_SZ / 32), 256>>>(W_attn, wa, K_SZ, N3_SZ);
    tsingle_kernel<<<dim3(M_SZ / 32, K_SZ / 32), 256>>>(W_proj, wp, K_SZ, M_SZ);

    gemm_mma_kernel<1><<<dim3(N3_SZ / 128, R_SZ / 128), 128, GT_SMEM>>>(
        xh, wa, b_attn, nullptr, N3_SZ, qh, ql, kk, vv);

    attn_mma_kernel<<<dim3(P_SZ / 128, BH_SZ), 128, AT_SMEM>>>(
        qh, ql, kk, vv, zz);

    gemm_mma_kernel<0><<<dim3(M_SZ / 128, R_SZ / 128), 128, GT_SMEM>>>(
        zz, wp, b_proj, out, M_SZ,
        nullptr, nullptr, nullptr, nullptr);
}